// round 9
// baseline (speedup 1.0000x reference)
#include <cuda_runtime.h>
#include <cuda_fp16.h>
#include <cstdint>

#define N_LEVELS 16
#define LOG2_T 19
#define HASH_MASK ((1u << LOG2_T) - 1u)
#define P0 73856093u
#define P1 19349663u
#define P2 83492791u

// floor(16 * 2^(l/3)) through the reference fp32 chain (verified in R1).
__device__ constexpr float c_resf[N_LEVELS] = {
    16.f, 20.f, 25.f, 32.f, 40.f, 50.f, 64.f, 80.f,
    101.f, 128.f, 161.f, 203.f, 256.f, 322.f, 406.f, 512.f
};

// Dense levels 0..8: fp16 2x2 yz-corner-block tables (16B entries).
#define N_DENSE 9
__device__ constexpr int c_sy[N_DENSE]  = {17, 21, 26, 33, 41, 51, 65, 81, 102};
__device__ constexpr int c_sx[N_DENSE]  = {289, 441, 676, 1089, 1681, 2601, 4225, 6561, 10404};
__device__ constexpr int c_OFF[N_DENSE] = {
    0, 5202, 14904, 33156, 70182, 140784, 276036, 554886, 1092888
};
#define DENSE_TOTAL 2164500
__device__ uint4 g_dense[DENSE_TOTAL];       // 34.6 MB

// Level 9 (res=128): fp16 z-pair table, 8B entries keyed by (cx,cy corner, bz cell).
// g_l9[(cx*130 + cy)*129 + bz] = { h2(E[cx,cy,bz]), h2(E[cx,cy,bz+1]) }
#define L9_ENTRIES (130 * 130 * 129)         // 2,180,100 -> 17.4 MB
__device__ uint2 g_l9[L9_ENTRIES];

__device__ __forceinline__ unsigned pack_h2(float a, float b) {
    __half2 h = __floats2half2_rn(a, b);
    return *reinterpret_cast<unsigned*>(&h);
}

// ================= fused strip prepass (ONE kernel, levels 0..9) =================
// Each thread builds 4 consecutive-z entries, sharing z-corner gathers.
__device__ constexpr int kSOFF[11] = {
    0, 1530, 4302, 9216, 19314, 38256, 72732, 145662, 285144, 558300, 1116000
};
#define TOTAL_STRIPS 1116000
__device__ constexpr int kR[10] = {16, 20, 25, 32, 40, 50, 64, 80, 101, 128};

template<int L>
__device__ __forceinline__ void do_level(int loc, const float2* __restrict__ embb)
{
    const float2* tbl = embb + ((size_t)L << LOG2_T);

    if constexpr (L < 9) {
        constexpr int R   = kR[L];
        constexpr int ny  = R + 1;                 // by extent
        constexpr int nsz = (R + 4) / 4;           // ceil((R+1)/4) z-strips
        constexpr int sx  = (R + 1) * (R + 1);
        constexpr int sy  = R + 1;

        int t  = loc / nsz;
        int sz = loc - t * nsz;
        int by = t % ny;
        int cx = t / ny;
        int bz0 = sz * 4;

        unsigned hx  = (unsigned)cx * P0;
        unsigned hy0 = (unsigned)by * P1, hy1 = hy0 + P1;

        float2 ey0[5], ey1[5];
        #pragma unroll
        for (int k = 0; k < 5; k++) {
            int zc = min(bz0 + k, R + 1);
            unsigned hz = (unsigned)zc * P2;
            ey0[k] = __ldg(tbl + ((hx ^ hy0 ^ hz) & HASH_MASK));
            ey1[k] = __ldg(tbl + ((hx ^ hy1 ^ hz) & HASH_MASK));
        }
        #pragma unroll
        for (int k = 0; k < 4; k++) {
            int bz = bz0 + k;
            if (bz <= R) {
                uint4 q;
                q.x = pack_h2(ey0[k].x,   ey0[k].y);
                q.y = pack_h2(ey0[k+1].x, ey0[k+1].y);
                q.z = pack_h2(ey1[k].x,   ey1[k].y);
                q.w = pack_h2(ey1[k+1].x, ey1[k+1].y);
                g_dense[c_OFF[L] + cx * sx + by * sy + bz] = q;
            }
        }
    } else {
        // level 9: z-pair entries keyed by corner (cx,cy), cell bz in [0,128]
        constexpr int nsz = 33;                    // ceil(129/4)
        int t  = loc / nsz;
        int sz = loc - t * nsz;
        int cy = t % 130;
        int cx = t / 130;
        int bz0 = sz * 4;

        unsigned hx = (unsigned)cx * P0;
        unsigned hy = (unsigned)cy * P1;

        float2 e[5];
        #pragma unroll
        for (int k = 0; k < 5; k++) {
            int zc = min(bz0 + k, 129);
            unsigned hz = (unsigned)zc * P2;
            e[k] = __ldg(tbl + ((hx ^ hy ^ hz) & HASH_MASK));
        }
        int rowbase = (cx * 130 + cy) * 129;
        #pragma unroll
        for (int k = 0; k < 4; k++) {
            int bz = bz0 + k;
            if (bz <= 128)
                g_l9[rowbase + bz] = make_uint2(pack_h2(e[k].x, e[k].y),
                                                pack_h2(e[k+1].x, e[k+1].y));
        }
    }
}

template<int L>
__device__ __forceinline__ void dispatch_level(int idx, const float2* __restrict__ embb)
{
    if constexpr (L < 10) {
        if (idx < kSOFF[L + 1]) do_level<L>(idx - kSOFF[L], embb);
        else dispatch_level<L + 1>(idx, embb);
    }
}

__global__ void __launch_bounds__(256) build_fused(const float* __restrict__ emb)
{
    int idx = blockIdx.x * blockDim.x + threadIdx.x;
    if (idx >= TOTAL_STRIPS) return;
    dispatch_level<0>(idx, (const float2*)emb);
}

// ================= main kernel =================
__global__ void __launch_bounds__(256) hashenc_kernel(
    const float* __restrict__ x,
    const float* __restrict__ emb,
    float* __restrict__ out,
    int B)
{
    const int lane = threadIdx.x & 31;
    const int warp = threadIdx.x >> 5;
    const int i = blockIdx.x * blockDim.x + threadIdx.x;
    const int warpBase = i - lane;
    if (warpBase >= B) return;
    const bool active = (i < B);
    const int ii = active ? i : (B - 1);

    float px = x[3 * ii + 0];
    float py = x[3 * ii + 1];
    float pz = x[3 * ii + 2];
    px = fminf(fmaxf(px, -1.0f), 1.0f);
    py = fminf(fmaxf(py, -1.0f), 1.0f);
    pz = fminf(fmaxf(pz, -1.0f), 1.0f);

    float o[2 * N_LEVELS];

    #pragma unroll
    for (int l = 0; l < N_LEVELS; l++) {
        // fast cell/weight math (trilinear continuity: 1-ulp floor
        // disagreements vs reference perturb output by ~1e-9)
        const float hres = 0.5f * c_resf[l];
        float tx = fmaf(px, hres, hres);
        float ty = fmaf(py, hres, hres);
        float tz = fmaf(pz, hres, hres);
        float fbx = floorf(tx), fby = floorf(ty), fbz = floorf(tz);
        int bx = (int)fbx, by = (int)fby, bz = (int)fbz;
        float wx = tx - fbx, wy = ty - fby, wz = tz - fbz;

        float wx0 = 1.0f - wx;
        float wy0 = 1.0f - wy;
        float wz0 = 1.0f - wz;

        float a0, a1;

        if (l < N_DENSE) {
            // dense fp16 2x2-block path: 2x LDG.128
            const int sy = c_sy[l];
            const int sx = c_sx[l];
            const uint4* dp = g_dense + c_OFF[l];
            int base = bx * sx + by * sy + bz;
            uint4 q0 = __ldg(dp + base);
            uint4 q1 = __ldg(dp + base + sx);

            float wyz00 = wy0 * wz0;
            float wyz01 = wy0 * wz;
            float wyz10 = wy  * wz0;
            float wyz11 = wy  * wz;

            float2 f00 = __half22float2(*reinterpret_cast<__half2*>(&q0.x));
            float2 f01 = __half22float2(*reinterpret_cast<__half2*>(&q0.y));
            float2 f10 = __half22float2(*reinterpret_cast<__half2*>(&q0.z));
            float2 f11 = __half22float2(*reinterpret_cast<__half2*>(&q0.w));
            float v0x = wyz00 * f00.x;           float v0y = wyz00 * f00.y;
            v0x = fmaf(wyz01, f01.x, v0x);       v0y = fmaf(wyz01, f01.y, v0y);
            v0x = fmaf(wyz10, f10.x, v0x);       v0y = fmaf(wyz10, f10.y, v0y);
            v0x = fmaf(wyz11, f11.x, v0x);       v0y = fmaf(wyz11, f11.y, v0y);

            float2 g00 = __half22float2(*reinterpret_cast<__half2*>(&q1.x));
            float2 g01 = __half22float2(*reinterpret_cast<__half2*>(&q1.y));
            float2 g10 = __half22float2(*reinterpret_cast<__half2*>(&q1.z));
            float2 g11 = __half22float2(*reinterpret_cast<__half2*>(&q1.w));
            float v1x = wyz00 * g00.x;           float v1y = wyz00 * g00.y;
            v1x = fmaf(wyz01, g01.x, v1x);       v1y = fmaf(wyz01, g01.y, v1y);
            v1x = fmaf(wyz10, g10.x, v1x);       v1y = fmaf(wyz10, g10.y, v1y);
            v1x = fmaf(wyz11, g11.x, v1x);       v1y = fmaf(wyz11, g11.y, v1y);

            a0 = fmaf(wx, v1x, wx0 * v0x);
            a1 = fmaf(wx, v1y, wx0 * v0y);
        } else if (l == 9) {
            // level-9 z-pair path: 4x LDG.64
            int base = (bx * 130 + by) * 129 + bz;
            uint2 p00 = __ldg(g_l9 + base);
            uint2 p01 = __ldg(g_l9 + base + 129);
            uint2 p10 = __ldg(g_l9 + base + 130 * 129);
            uint2 p11 = __ldg(g_l9 + base + 130 * 129 + 129);

            float2 a00 = __half22float2(*reinterpret_cast<__half2*>(&p00.x));
            float2 b00 = __half22float2(*reinterpret_cast<__half2*>(&p00.y));
            float2 a01 = __half22float2(*reinterpret_cast<__half2*>(&p01.x));
            float2 b01 = __half22float2(*reinterpret_cast<__half2*>(&p01.y));
            float2 a10 = __half22float2(*reinterpret_cast<__half2*>(&p10.x));
            float2 b10 = __half22float2(*reinterpret_cast<__half2*>(&p10.y));
            float2 a11 = __half22float2(*reinterpret_cast<__half2*>(&p11.x));
            float2 b11 = __half22float2(*reinterpret_cast<__half2*>(&p11.y));

            // z-lerp per (x,y) corner
            float m00x = fmaf(wz, b00.x, wz0 * a00.x), m00y = fmaf(wz, b00.y, wz0 * a00.y);
            float m01x = fmaf(wz, b01.x, wz0 * a01.x), m01y = fmaf(wz, b01.y, wz0 * a01.y);
            float m10x = fmaf(wz, b10.x, wz0 * a10.x), m10y = fmaf(wz, b10.y, wz0 * a10.y);
            float m11x = fmaf(wz, b11.x, wz0 * a11.x), m11y = fmaf(wz, b11.y, wz0 * a11.y);

            float cxy00 = wx0 * wy0;
            float cxy01 = wx0 * wy;
            float cxy10 = wx  * wy0;
            float cxy11 = wx  * wy;

            a0 = cxy00 * m00x;            a1 = cxy00 * m00y;
            a0 = fmaf(cxy01, m01x, a0);   a1 = fmaf(cxy01, m01y, a1);
            a0 = fmaf(cxy10, m10x, a0);   a1 = fmaf(cxy10, m10y, a1);
            a0 = fmaf(cxy11, m11x, a0);   a1 = fmaf(cxy11, m11y, a1);
        } else {
            // hashed fp32 path: 8x LDG.64
            unsigned hx0 = (unsigned)bx * P0, hx1 = hx0 + P0;
            unsigned hy0 = (unsigned)by * P1, hy1 = hy0 + P1;
            unsigned hz0 = (unsigned)bz * P2, hz1 = hz0 + P2;

            unsigned h0 = (hx0 ^ hy0 ^ hz0) & HASH_MASK;
            unsigned h1 = (hx0 ^ hy0 ^ hz1) & HASH_MASK;
            unsigned h2 = (hx0 ^ hy1 ^ hz0) & HASH_MASK;
            unsigned h3 = (hx0 ^ hy1 ^ hz1) & HASH_MASK;
            unsigned h4 = (hx1 ^ hy0 ^ hz0) & HASH_MASK;
            unsigned h5 = (hx1 ^ hy0 ^ hz1) & HASH_MASK;
            unsigned h6 = (hx1 ^ hy1 ^ hz0) & HASH_MASK;
            unsigned h7 = (hx1 ^ hy1 ^ hz1) & HASH_MASK;

            const float2* tbl = (const float2*)emb + ((size_t)l << LOG2_T);
            float2 e0 = __ldg(tbl + h0);
            float2 e1 = __ldg(tbl + h1);
            float2 e2 = __ldg(tbl + h2);
            float2 e3 = __ldg(tbl + h3);
            float2 e4 = __ldg(tbl + h4);
            float2 e5 = __ldg(tbl + h5);
            float2 e6 = __ldg(tbl + h6);
            float2 e7 = __ldg(tbl + h7);

            float cxy00 = wx0 * wy0;
            float cxy01 = wx0 * wy;
            float cxy10 = wx  * wy0;
            float cxy11 = wx  * wy;

            float c0 = cxy00 * wz0, c1 = cxy00 * wz;
            float c2 = cxy01 * wz0, c3 = cxy01 * wz;
            float c4 = cxy10 * wz0, c5 = cxy10 * wz;
            float c6 = cxy11 * wz0, c7 = cxy11 * wz;

            a0 = c0 * e0.x;            a1 = c0 * e0.y;
            a0 = fmaf(c1, e1.x, a0);   a1 = fmaf(c1, e1.y, a1);
            a0 = fmaf(c2, e2.x, a0);   a1 = fmaf(c2, e2.y, a1);
            a0 = fmaf(c3, e3.x, a0);   a1 = fmaf(c3, e3.y, a1);
            a0 = fmaf(c4, e4.x, a0);   a1 = fmaf(c4, e4.y, a1);
            a0 = fmaf(c5, e5.x, a0);   a1 = fmaf(c5, e5.y, a1);
            a0 = fmaf(c6, e6.x, a0);   a1 = fmaf(c6, e6.y, a1);
            a0 = fmaf(c7, e7.x, a0);   a1 = fmaf(c7, e7.y, a1);
        }

        o[2 * l + 0] = a0;
        o[2 * l + 1] = a1;
    }

    // ---- coalesced output via warp-level smem transpose (deferred, batched) ----
    __shared__ float4 sbuf[8 * 32 * 9];
    float4* wb = sbuf + warp * (32 * 9);

    if (warpBase + 32 <= B) {
        #pragma unroll
        for (int s = 0; s < 8; s++)
            wb[lane * 9 + s] = make_float4(o[4*s+0], o[4*s+1], o[4*s+2], o[4*s+3]);
        __syncwarp();
        float4* ob = (float4*)out + (size_t)warpBase * 8;
        #pragma unroll
        for (int k = 0; k < 8; k++) {
            int r = k * 4 + (lane >> 3);
            int s = lane & 7;
            __stcs(ob + k * 32 + lane, wb[r * 9 + s]);   // streaming: protect L2 hot set
        }
    } else if (active) {
        float4* po = (float4*)(out + (size_t)i * (2 * N_LEVELS));
        #pragma unroll
        for (int s = 0; s < 8; s++)
            __stcs(po + s, make_float4(o[4*s+0], o[4*s+1], o[4*s+2], o[4*s+3]));
    }
}

extern "C" void kernel_launch(void* const* d_in, const int* in_sizes, int n_in,
                              void* d_out, int out_size) {
    const float* x   = (const float*)d_in[0];
    const float* emb = (const float*)d_in[1];
    float* out = (float*)d_out;
    const int B = in_sizes[0] / 3;

    build_fused<<<(TOTAL_STRIPS + 255) / 256, 256>>>(emb);

    const int threads = 256;
    const int blocks = (B + threads - 1) / threads;
    hashenc_kernel<<<blocks, threads>>>(x, emb, out, B);
}

// round 10
// speedup vs baseline: 1.0624x; 1.0624x over previous
#include <cuda_runtime.h>
#include <cuda_fp16.h>
#include <cstdint>

#define N_LEVELS 16
#define LOG2_T 19
#define HASH_MASK ((1u << LOG2_T) - 1u)
#define P0 73856093u
#define P1 19349663u
#define P2 83492791u

// floor(16 * 2^(l/3)) through the reference fp32 chain (verified in R1).
__device__ constexpr float c_resf[N_LEVELS] = {
    16.f, 20.f, 25.f, 32.f, 40.f, 50.f, 64.f, 80.f,
    101.f, 128.f, 161.f, 203.f, 256.f, 322.f, 406.f, 512.f
};

// Dense levels 0..9: fp16 2x2 yz-corner-block tables (16B entries).
// Entry (cx, by, bz): cx in [0,R+1], by,bz in [0,R]:
//   uint4 = { h2(y0z0), h2(y0z1), h2(y1z0), h2(y1z1) }
#define N_DENSE 10
__device__ constexpr int c_Rd[N_DENSE]  = {16, 20, 25, 32, 40, 50, 64, 80, 101, 128};
__device__ constexpr int c_sy[N_DENSE]  = {17, 21, 26, 33, 41, 51, 65, 81, 102, 129};
__device__ constexpr int c_sx[N_DENSE]  = {289, 441, 676, 1089, 1681, 2601, 4225, 6561, 10404, 16641};
__device__ constexpr int c_OFF[N_DENSE] = {
    0, 5202, 14904, 33156, 70182, 140784, 276036, 554886, 1092888, 2164500
};
#define DENSE_TOTAL 4327830
__device__ uint4 g_dense[DENSE_TOTAL];       // 69.2 MB

__device__ __forceinline__ unsigned pack_h2(float a, float b) {
    __half2 h = __floats2half2_rn(a, b);
    return *reinterpret_cast<unsigned*>(&h);
}

// ============ single-launch smem-tiled prepass (levels 0..9) ============
// One block = (level, cx, 16x16 yz cell tile). 17x17 corner halo staged in
// smem (each corner gathered once per tile), entries assembled from smem.
__device__ constexpr int c_NT[N_DENSE] = {2, 2, 2, 3, 3, 4, 5, 6, 7, 9};  // ceil((R+1)/16)
__device__ constexpr int c_BOFF[N_DENSE + 1] = {
    0, 72, 160, 268, 574, 952, 1784, 3434, 6386, 11433, 21963
};
#define TOTAL_BLOCKS 21963

__global__ void __launch_bounds__(256) build_tiled(const float* __restrict__ emb)
{
    // decode (level, cx, ty, tz) from blockIdx
    int b = blockIdx.x;
    int L = 0;
    #pragma unroll
    for (int k = 1; k < N_DENSE; k++)
        if (b >= c_BOFF[k]) L = k;
    int loc = b - c_BOFF[L];
    const int nt = c_NT[L];
    const int R  = c_Rd[L];

    int tz = loc % nt;
    int t2 = loc / nt;
    int ty = t2 % nt;
    int cx = t2 / nt;
    int y0 = ty * 16;
    int z0 = tz * 16;

    __shared__ unsigned sc[17 * 17];

    const float2* tbl = (const float2*)emb + ((size_t)L << LOG2_T);
    const unsigned hx = (unsigned)cx * P0;

    // stage the 17x17 corner halo (clamped at edges; duplicates harmless)
    for (int idx = threadIdx.x; idx < 289; idx += 256) {
        int dy = idx / 17;
        int dz = idx - dy * 17;
        int cy = min(y0 + dy, R + 1);
        int cz = min(z0 + dz, R + 1);
        unsigned h = (hx ^ ((unsigned)cy * P1) ^ ((unsigned)cz * P2)) & HASH_MASK;
        float2 e = __ldg(tbl + h);
        sc[idx] = pack_h2(e.x, e.y);
    }
    __syncthreads();

    // each thread assembles one 16B block entry (coalesced write along bz)
    int dy = threadIdx.x >> 4;
    int dz = threadIdx.x & 15;
    int by = y0 + dy;
    int bz = z0 + dz;
    if (by <= R && bz <= R) {
        uint4 q;
        q.x = sc[dy * 17 + dz];
        q.y = sc[dy * 17 + dz + 1];
        q.z = sc[(dy + 1) * 17 + dz];
        q.w = sc[(dy + 1) * 17 + dz + 1];
        g_dense[c_OFF[L] + cx * c_sx[L] + by * c_sy[L] + bz] = q;
    }
}

// ================= main kernel (R8-proven body, N_DENSE=10) =================
__global__ void __launch_bounds__(256) hashenc_kernel(
    const float* __restrict__ x,
    const float* __restrict__ emb,
    float* __restrict__ out,
    int B)
{
    const int lane = threadIdx.x & 31;
    const int warp = threadIdx.x >> 5;
    const int i = blockIdx.x * blockDim.x + threadIdx.x;
    const int warpBase = i - lane;
    if (warpBase >= B) return;
    const bool active = (i < B);
    const int ii = active ? i : (B - 1);

    float px = x[3 * ii + 0];
    float py = x[3 * ii + 1];
    float pz = x[3 * ii + 2];
    px = fminf(fmaxf(px, -1.0f), 1.0f);
    py = fminf(fmaxf(py, -1.0f), 1.0f);
    pz = fminf(fmaxf(pz, -1.0f), 1.0f);

    float o[2 * N_LEVELS];

    #pragma unroll
    for (int l = 0; l < N_LEVELS; l++) {
        // fast cell/weight math (trilinear continuity: 1-ulp floor
        // disagreements vs reference perturb output by ~1e-9)
        const float hres = 0.5f * c_resf[l];
        float tx = fmaf(px, hres, hres);
        float ty = fmaf(py, hres, hres);
        float tz = fmaf(pz, hres, hres);
        float fbx = floorf(tx), fby = floorf(ty), fbz = floorf(tz);
        int bx = (int)fbx, by = (int)fby, bz = (int)fbz;
        float wx = tx - fbx, wy = ty - fby, wz = tz - fbz;

        float wx0 = 1.0f - wx;
        float wy0 = 1.0f - wy;
        float wz0 = 1.0f - wz;

        float a0, a1;

        if (l < N_DENSE) {
            // dense fp16 2x2-block path: 2x LDG.128
            const int sy = c_sy[l];
            const int sx = c_sx[l];
            const uint4* dp = g_dense + c_OFF[l];
            int base = bx * sx + by * sy + bz;
            uint4 q0 = __ldg(dp + base);
            uint4 q1 = __ldg(dp + base + sx);

            float wyz00 = wy0 * wz0;
            float wyz01 = wy0 * wz;
            float wyz10 = wy  * wz0;
            float wyz11 = wy  * wz;

            float2 f00 = __half22float2(*reinterpret_cast<__half2*>(&q0.x));
            float2 f01 = __half22float2(*reinterpret_cast<__half2*>(&q0.y));
            float2 f10 = __half22float2(*reinterpret_cast<__half2*>(&q0.z));
            float2 f11 = __half22float2(*reinterpret_cast<__half2*>(&q0.w));
            float v0x = wyz00 * f00.x;           float v0y = wyz00 * f00.y;
            v0x = fmaf(wyz01, f01.x, v0x);       v0y = fmaf(wyz01, f01.y, v0y);
            v0x = fmaf(wyz10, f10.x, v0x);       v0y = fmaf(wyz10, f10.y, v0y);
            v0x = fmaf(wyz11, f11.x, v0x);       v0y = fmaf(wyz11, f11.y, v0y);

            float2 g00 = __half22float2(*reinterpret_cast<__half2*>(&q1.x));
            float2 g01 = __half22float2(*reinterpret_cast<__half2*>(&q1.y));
            float2 g10 = __half22float2(*reinterpret_cast<__half2*>(&q1.z));
            float2 g11 = __half22float2(*reinterpret_cast<__half2*>(&q1.w));
            float v1x = wyz00 * g00.x;           float v1y = wyz00 * g00.y;
            v1x = fmaf(wyz01, g01.x, v1x);       v1y = fmaf(wyz01, g01.y, v1y);
            v1x = fmaf(wyz10, g10.x, v1x);       v1y = fmaf(wyz10, g10.y, v1y);
            v1x = fmaf(wyz11, g11.x, v1x);       v1y = fmaf(wyz11, g11.y, v1y);

            a0 = fmaf(wx, v1x, wx0 * v0x);
            a1 = fmaf(wx, v1y, wx0 * v0y);
        } else {
            // hashed fp32 path: 8x LDG.64
            unsigned hx0 = (unsigned)bx * P0, hx1 = hx0 + P0;
            unsigned hy0 = (unsigned)by * P1, hy1 = hy0 + P1;
            unsigned hz0 = (unsigned)bz * P2, hz1 = hz0 + P2;

            unsigned h0 = (hx0 ^ hy0 ^ hz0) & HASH_MASK;
            unsigned h1 = (hx0 ^ hy0 ^ hz1) & HASH_MASK;
            unsigned h2 = (hx0 ^ hy1 ^ hz0) & HASH_MASK;
            unsigned h3 = (hx0 ^ hy1 ^ hz1) & HASH_MASK;
            unsigned h4 = (hx1 ^ hy0 ^ hz0) & HASH_MASK;
            unsigned h5 = (hx1 ^ hy0 ^ hz1) & HASH_MASK;
            unsigned h6 = (hx1 ^ hy1 ^ hz0) & HASH_MASK;
            unsigned h7 = (hx1 ^ hy1 ^ hz1) & HASH_MASK;

            const float2* tbl = (const float2*)emb + ((size_t)l << LOG2_T);
            float2 e0 = __ldg(tbl + h0);
            float2 e1 = __ldg(tbl + h1);
            float2 e2 = __ldg(tbl + h2);
            float2 e3 = __ldg(tbl + h3);
            float2 e4 = __ldg(tbl + h4);
            float2 e5 = __ldg(tbl + h5);
            float2 e6 = __ldg(tbl + h6);
            float2 e7 = __ldg(tbl + h7);

            float cxy00 = wx0 * wy0;
            float cxy01 = wx0 * wy;
            float cxy10 = wx  * wy0;
            float cxy11 = wx  * wy;

            float c0 = cxy00 * wz0, c1 = cxy00 * wz;
            float c2 = cxy01 * wz0, c3 = cxy01 * wz;
            float c4 = cxy10 * wz0, c5 = cxy10 * wz;
            float c6 = cxy11 * wz0, c7 = cxy11 * wz;

            a0 = c0 * e0.x;            a1 = c0 * e0.y;
            a0 = fmaf(c1, e1.x, a0);   a1 = fmaf(c1, e1.y, a1);
            a0 = fmaf(c2, e2.x, a0);   a1 = fmaf(c2, e2.y, a1);
            a0 = fmaf(c3, e3.x, a0);   a1 = fmaf(c3, e3.y, a1);
            a0 = fmaf(c4, e4.x, a0);   a1 = fmaf(c4, e4.y, a1);
            a0 = fmaf(c5, e5.x, a0);   a1 = fmaf(c5, e5.y, a1);
            a0 = fmaf(c6, e6.x, a0);   a1 = fmaf(c6, e6.y, a1);
            a0 = fmaf(c7, e7.x, a0);   a1 = fmaf(c7, e7.y, a1);
        }

        o[2 * l + 0] = a0;
        o[2 * l + 1] = a1;
    }

    // ---- coalesced output via warp-level smem transpose (deferred, batched) ----
    __shared__ float4 sbuf[8 * 32 * 9];
    float4* wb = sbuf + warp * (32 * 9);

    if (warpBase + 32 <= B) {
        #pragma unroll
        for (int s = 0; s < 8; s++)
            wb[lane * 9 + s] = make_float4(o[4*s+0], o[4*s+1], o[4*s+2], o[4*s+3]);
        __syncwarp();
        float4* ob = (float4*)out + (size_t)warpBase * 8;
        #pragma unroll
        for (int k = 0; k < 8; k++) {
            int r = k * 4 + (lane >> 3);
            int s = lane & 7;
            __stcs(ob + k * 32 + lane, wb[r * 9 + s]);   // streaming: protect L2 hot set
        }
    } else if (active) {
        float4* po = (float4*)(out + (size_t)i * (2 * N_LEVELS));
        #pragma unroll
        for (int s = 0; s < 8; s++)
            __stcs(po + s, make_float4(o[4*s+0], o[4*s+1], o[4*s+2], o[4*s+3]));
    }
}

extern "C" void kernel_launch(void* const* d_in, const int* in_sizes, int n_in,
                              void* d_out, int out_size) {
    const float* x   = (const float*)d_in[0];
    const float* emb = (const float*)d_in[1];
    float* out = (float*)d_out;
    const int B = in_sizes[0] / 3;

    build_tiled<<<TOTAL_BLOCKS, 256>>>(emb);

    const int threads = 256;
    const int blocks = (B + threads - 1) / threads;
    hashenc_kernel<<<blocks, threads>>>(x, emb, out, B);
}

// round 11
// speedup vs baseline: 1.1076x; 1.0426x over previous
#include <cuda_runtime.h>
#include <cuda_fp16.h>
#include <cstdint>

#define N_LEVELS 16
#define LOG2_T 19
#define HASH_MASK ((1u << LOG2_T) - 1u)
#define P0 73856093u
#define P1 19349663u
#define P2 83492791u

// floor(16 * 2^(l/3)) through the reference fp32 chain (verified in R1).
__device__ constexpr float c_resf[N_LEVELS] = {
    16.f, 20.f, 25.f, 32.f, 40.f, 50.f, 64.f, 80.f,
    101.f, 128.f, 161.f, 203.f, 256.f, 322.f, 406.f, 512.f
};

// Dense levels 0..8: fp16 2x2 yz-corner-block tables (16B entries).
#define N_DENSE 9
__device__ constexpr int c_sy[N_DENSE]  = {17, 21, 26, 33, 41, 51, 65, 81, 102};
__device__ constexpr int c_sx[N_DENSE]  = {289, 441, 676, 1089, 1681, 2601, 4225, 6561, 10404};
__device__ constexpr int c_OFF[N_DENSE] = {
    0, 5202, 14904, 33156, 70182, 140784, 276036, 554886, 1092888
};
#define DENSE_TOTAL 2164500
__device__ uint4 g_dense[DENSE_TOTAL];       // 34.6 MB, L2-resident

// Corner tables: C[cx][cy][cz], dims (R+2)^3, packed fp16x2 per corner.
__device__ constexpr int c_cd[N_DENSE]   = {18, 22, 27, 34, 42, 52, 66, 82, 103};
__device__ constexpr int c_COFF[N_DENSE] = {
    0, 5832, 16480, 36163, 75467, 149555, 290163, 577659, 1129027
};
#define CORNER_TOTAL 2221754
__device__ unsigned g_corner[CORNER_TOTAL];  // 8.9 MB (transient)

// magic-number unsigned division: exact for u < 2^22, d <= 130
constexpr unsigned long long magic(unsigned d) { return ((1ULL << 40) / d) + 1ULL; }
__device__ constexpr unsigned long long c_mcd[N_DENSE] = {
    magic(18), magic(22), magic(27), magic(34), magic(42),
    magic(52), magic(66), magic(82), magic(103)
};
__device__ constexpr unsigned long long c_msy[N_DENSE] = {
    magic(17), magic(21), magic(26), magic(33), magic(41),
    magic(51), magic(65), magic(81), magic(102)
};
__device__ __forceinline__ unsigned mdiv(unsigned u, unsigned long long M) {
    return (unsigned)(((unsigned long long)u * M) >> 40);
}

__device__ __forceinline__ unsigned pack_h2(float a, float b) {
    __half2 h = __floats2half2_rn(a, b);
    return *reinterpret_cast<unsigned*>(&h);
}

// ------- prepass stage 1: gather each corner once (4/thread, MLP=4) -------
__global__ void __launch_bounds__(256) build_corners(const float* __restrict__ emb)
{
    const unsigned tid = blockIdx.x * blockDim.x + threadIdx.x;
    const unsigned S = gridDim.x * blockDim.x;

    unsigned hh[4];
    int lv[4];
    bool ok[4];
    #pragma unroll
    for (int k = 0; k < 4; k++) {
        unsigned idx = tid + k * S;
        ok[k] = (idx < CORNER_TOTAL);
        unsigned cidx = ok[k] ? idx : 0u;
        int l = 0;
        #pragma unroll
        for (int m = 1; m < N_DENSE; m++)
            if (cidx >= (unsigned)c_COFF[m]) l = m;
        unsigned loc = cidx - (unsigned)c_COFF[l];
        unsigned t  = mdiv(loc, c_mcd[l]);          // loc / d
        unsigned cz = loc - t * (unsigned)c_cd[l];
        unsigned cx = mdiv(t, c_mcd[l]);            // t / d
        unsigned cy = t - cx * (unsigned)c_cd[l];
        hh[k] = ((cx * P0) ^ (cy * P1) ^ (cz * P2)) & HASH_MASK;
        lv[k] = l;
    }

    // all 4 gathers in flight before any consumption
    float2 e[4];
    #pragma unroll
    for (int k = 0; k < 4; k++) {
        const float2* tbl = (const float2*)emb + ((size_t)lv[k] << LOG2_T);
        e[k] = __ldg(tbl + hh[k]);
    }

    #pragma unroll
    for (int k = 0; k < 4; k++)
        if (ok[k])
            g_corner[tid + k * S] = pack_h2(e[k].x, e[k].y);  // coalesced sweep per k
}

// ------- prepass stage 2: assemble 2x2 yz-blocks (coalesced reads/writes) -------
__global__ void __launch_bounds__(256) build_blocks()
{
    unsigned idx = blockIdx.x * blockDim.x + threadIdx.x;
    if (idx >= DENSE_TOTAL) return;

    int l = 0;
    #pragma unroll
    for (int m = 1; m < N_DENSE; m++)
        if (idx >= (unsigned)c_OFF[m]) l = m;
    unsigned loc = idx - (unsigned)c_OFF[l];
    unsigned sy = (unsigned)c_sy[l];

    unsigned t  = mdiv(loc, c_msy[l]);              // loc / sy
    unsigned bz = loc - t * sy;
    unsigned cx = mdiv(t, c_msy[l]);                // t / sy
    unsigned by = t - cx * sy;

    unsigned d = (unsigned)c_cd[l];
    const unsigned* C = g_corner + c_COFF[l];
    unsigned cb = (cx * d + by) * d + bz;

    uint4 q;
    q.x = C[cb];           // (y0,z0)
    q.y = C[cb + 1];       // (y0,z1)
    q.z = C[cb + d];       // (y1,z0)
    q.w = C[cb + d + 1];   // (y1,z1)
    g_dense[idx] = q;
}

// ================= main kernel (R7-proven body, 282.7us) =================
__global__ void __launch_bounds__(256) hashenc_kernel(
    const float* __restrict__ x,
    const float* __restrict__ emb,
    float* __restrict__ out,
    int B)
{
    const int lane = threadIdx.x & 31;
    const int warp = threadIdx.x >> 5;
    const int i = blockIdx.x * blockDim.x + threadIdx.x;
    const int warpBase = i - lane;
    if (warpBase >= B) return;
    const bool active = (i < B);
    const int ii = active ? i : (B - 1);

    float px = x[3 * ii + 0];
    float py = x[3 * ii + 1];
    float pz = x[3 * ii + 2];
    px = fminf(fmaxf(px, -1.0f), 1.0f);
    py = fminf(fmaxf(py, -1.0f), 1.0f);
    pz = fminf(fmaxf(pz, -1.0f), 1.0f);

    float o[2 * N_LEVELS];

    #pragma unroll
    for (int l = 0; l < N_LEVELS; l++) {
        // fast cell/weight math (trilinear continuity: 1-ulp floor
        // disagreements vs reference perturb output by ~1e-9)
        const float hres = 0.5f * c_resf[l];
        float tx = fmaf(px, hres, hres);
        float ty = fmaf(py, hres, hres);
        float tz = fmaf(pz, hres, hres);
        float fbx = floorf(tx), fby = floorf(ty), fbz = floorf(tz);
        int bx = (int)fbx, by = (int)fby, bz = (int)fbz;
        float wx = tx - fbx, wy = ty - fby, wz = tz - fbz;

        float wx0 = 1.0f - wx;
        float wy0 = 1.0f - wy;
        float wz0 = 1.0f - wz;

        float a0, a1;

        if (l < N_DENSE) {
            // dense fp16 2x2-block path: 2x LDG.128
            const int sy = c_sy[l];
            const int sx = c_sx[l];
            const uint4* dp = g_dense + c_OFF[l];
            int base = bx * sx + by * sy + bz;
            uint4 q0 = __ldg(dp + base);
            uint4 q1 = __ldg(dp + base + sx);

            float wyz00 = wy0 * wz0;
            float wyz01 = wy0 * wz;
            float wyz10 = wy  * wz0;
            float wyz11 = wy  * wz;

            float2 f00 = __half22float2(*reinterpret_cast<__half2*>(&q0.x));
            float2 f01 = __half22float2(*reinterpret_cast<__half2*>(&q0.y));
            float2 f10 = __half22float2(*reinterpret_cast<__half2*>(&q0.z));
            float2 f11 = __half22float2(*reinterpret_cast<__half2*>(&q0.w));
            float v0x = wyz00 * f00.x;           float v0y = wyz00 * f00.y;
            v0x = fmaf(wyz01, f01.x, v0x);       v0y = fmaf(wyz01, f01.y, v0y);
            v0x = fmaf(wyz10, f10.x, v0x);       v0y = fmaf(wyz10, f10.y, v0y);
            v0x = fmaf(wyz11, f11.x, v0x);       v0y = fmaf(wyz11, f11.y, v0y);

            float2 g00 = __half22float2(*reinterpret_cast<__half2*>(&q1.x));
            float2 g01 = __half22float2(*reinterpret_cast<__half2*>(&q1.y));
            float2 g10 = __half22float2(*reinterpret_cast<__half2*>(&q1.z));
            float2 g11 = __half22float2(*reinterpret_cast<__half2*>(&q1.w));
            float v1x = wyz00 * g00.x;           float v1y = wyz00 * g00.y;
            v1x = fmaf(wyz01, g01.x, v1x);       v1y = fmaf(wyz01, g01.y, v1y);
            v1x = fmaf(wyz10, g10.x, v1x);       v1y = fmaf(wyz10, g10.y, v1y);
            v1x = fmaf(wyz11, g11.x, v1x);       v1y = fmaf(wyz11, g11.y, v1y);

            a0 = fmaf(wx, v1x, wx0 * v0x);
            a1 = fmaf(wx, v1y, wx0 * v0y);
        } else {
            // hashed fp32 path: 8x LDG.64
            unsigned hx0 = (unsigned)bx * P0, hx1 = hx0 + P0;
            unsigned hy0 = (unsigned)by * P1, hy1 = hy0 + P1;
            unsigned hz0 = (unsigned)bz * P2, hz1 = hz0 + P2;

            unsigned h0 = (hx0 ^ hy0 ^ hz0) & HASH_MASK;
            unsigned h1 = (hx0 ^ hy0 ^ hz1) & HASH_MASK;
            unsigned h2 = (hx0 ^ hy1 ^ hz0) & HASH_MASK;
            unsigned h3 = (hx0 ^ hy1 ^ hz1) & HASH_MASK;
            unsigned h4 = (hx1 ^ hy0 ^ hz0) & HASH_MASK;
            unsigned h5 = (hx1 ^ hy0 ^ hz1) & HASH_MASK;
            unsigned h6 = (hx1 ^ hy1 ^ hz0) & HASH_MASK;
            unsigned h7 = (hx1 ^ hy1 ^ hz1) & HASH_MASK;

            const float2* tbl = (const float2*)emb + ((size_t)l << LOG2_T);
            float2 e0 = __ldg(tbl + h0);
            float2 e1 = __ldg(tbl + h1);
            float2 e2 = __ldg(tbl + h2);
            float2 e3 = __ldg(tbl + h3);
            float2 e4 = __ldg(tbl + h4);
            float2 e5 = __ldg(tbl + h5);
            float2 e6 = __ldg(tbl + h6);
            float2 e7 = __ldg(tbl + h7);

            float cxy00 = wx0 * wy0;
            float cxy01 = wx0 * wy;
            float cxy10 = wx  * wy0;
            float cxy11 = wx  * wy;

            float c0 = cxy00 * wz0, c1 = cxy00 * wz;
            float c2 = cxy01 * wz0, c3 = cxy01 * wz;
            float c4 = cxy10 * wz0, c5 = cxy10 * wz;
            float c6 = cxy11 * wz0, c7 = cxy11 * wz;

            a0 = c0 * e0.x;            a1 = c0 * e0.y;
            a0 = fmaf(c1, e1.x, a0);   a1 = fmaf(c1, e1.y, a1);
            a0 = fmaf(c2, e2.x, a0);   a1 = fmaf(c2, e2.y, a1);
            a0 = fmaf(c3, e3.x, a0);   a1 = fmaf(c3, e3.y, a1);
            a0 = fmaf(c4, e4.x, a0);   a1 = fmaf(c4, e4.y, a1);
            a0 = fmaf(c5, e5.x, a0);   a1 = fmaf(c5, e5.y, a1);
            a0 = fmaf(c6, e6.x, a0);   a1 = fmaf(c6, e6.y, a1);
            a0 = fmaf(c7, e7.x, a0);   a1 = fmaf(c7, e7.y, a1);
        }

        o[2 * l + 0] = a0;
        o[2 * l + 1] = a1;
    }

    // ---- coalesced output via warp-level smem transpose (deferred, batched) ----
    __shared__ float4 sbuf[8 * 32 * 9];
    float4* wb = sbuf + warp * (32 * 9);

    if (warpBase + 32 <= B) {
        #pragma unroll
        for (int s = 0; s < 8; s++)
            wb[lane * 9 + s] = make_float4(o[4*s+0], o[4*s+1], o[4*s+2], o[4*s+3]);
        __syncwarp();
        float4* ob = (float4*)out + (size_t)warpBase * 8;
        #pragma unroll
        for (int k = 0; k < 8; k++) {
            int r = k * 4 + (lane >> 3);
            int s = lane & 7;
            __stcs(ob + k * 32 + lane, wb[r * 9 + s]);   // streaming: protect L2 hot set
        }
    } else if (active) {
        float4* po = (float4*)(out + (size_t)i * (2 * N_LEVELS));
        #pragma unroll
        for (int s = 0; s < 8; s++)
            __stcs(po + s, make_float4(o[4*s+0], o[4*s+1], o[4*s+2], o[4*s+3]));
    }
}

extern "C" void kernel_launch(void* const* d_in, const int* in_sizes, int n_in,
                              void* d_out, int out_size) {
    const float* x   = (const float*)d_in[0];
    const float* emb = (const float*)d_in[1];
    float* out = (float*)d_out;
    const int B = in_sizes[0] / 3;

    const int s1_threads = (CORNER_TOTAL + 3) / 4;         // 555,439
    build_corners<<<(s1_threads + 255) / 256, 256>>>(emb);
    build_blocks<<<(DENSE_TOTAL + 255) / 256, 256>>>();

    const int threads = 256;
    const int blocks = (B + threads - 1) / threads;
    hashenc_kernel<<<blocks, threads>>>(x, emb, out, B);
}